// round 8
// baseline (speedup 1.0000x reference)
#include <cuda_runtime.h>
#include <cuda_bf16.h>
#include <math.h>
#include <stdint.h>

// Problem constants
#define B_ 4
#define S_ 2048
#define H_ 16
#define D_ 64
#define DM_ 1024
#define M8_ 8192
#define BH_ 64
#define SCALE_ 0.125f
#define EPS_ 1e-6f

#define OUT_ELEMS   (M8_ * DM_)
#define ATTN_ELEMS  ((size_t)BH_ * S_ * S_)

// ---------------- device scratch -----------------------------------------------
__device__ float g_QH[(size_t)BH_ * S_ * D_];   // [B,H,S,D]
__device__ float g_KH[(size_t)BH_ * S_ * D_];
__device__ float g_VH[(size_t)BH_ * S_ * D_];
__device__ float g_AO[(size_t)M8_ * DM_];       // [B,S,H*D]
__device__ float g_FC[(size_t)M8_ * DM_];
__device__ float g_M[(size_t)BH_ * S_];
__device__ float g_L[(size_t)BH_ * S_];

// ---------------- tf32 helpers ---------------------------------------------------
// cvt.rna (round-to-nearest) is REQUIRED: raw truncation is biased toward zero and
// the bias accumulates coherently over K=64 dots -> attn rel_err 3e-3 (R5 failure).
__device__ __forceinline__ uint32_t f2tf32(float x) {
    uint32_t u;
    asm("cvt.rna.tf32.f32 %0, %1;" : "=r"(u) : "f"(x));
    return u;
}

__device__ __forceinline__ void mma8(float* c, const uint32_t* a, const uint32_t* b) {
    asm volatile(
        "mma.sync.aligned.m16n8k8.row.col.f32.tf32.tf32.f32 "
        "{%0,%1,%2,%3}, {%4,%5,%6,%7}, {%8,%9}, {%0,%1,%2,%3};"
        : "+f"(c[0]), "+f"(c[1]), "+f"(c[2]), "+f"(c[3])
        : "r"(a[0]), "r"(a[1]), "r"(a[2]), "r"(a[3]), "r"(b[0]), "r"(b[1]));
}

// =================================================================================
// tf32 GEMM: C[M,N] = A[M,K] @ W[N,K]^T (+resid). 128x128 tile, BK=32, 256 thr.
// Double-buffered: register prefetch of tile k+1 overlaps compute of tile k.
// =================================================================================
#define GEMM_SMEM_BYTES (4 * 128 * 36 * 4)

__global__ __launch_bounds__(256) void gemm_tf32_kernel(
    const float* __restrict__ A, const float* __restrict__ W, float* __restrict__ C,
    int K, int headmajor, const float* __restrict__ resid) {
    extern __shared__ uint32_t dynsm[];
    uint32_t* As = dynsm;              // 2 buffers of [128][36]
    uint32_t* Ws = dynsm + 2 * 4608;   // 2 buffers of [128][36]

    const int tid = threadIdx.x;
    const int lane = tid & 31, warp = tid >> 5;
    const int wm = warp >> 1, wn = warp & 1;
    const int rm = wm * 32, cn = wn * 64;
    const int m0 = blockIdx.y * 128, n0 = blockIdx.x * 128;

    const int lr0 = tid >> 3, lr1 = (tid + 256) >> 3, lr2 = (tid + 512) >> 3, lr3 = (tid + 768) >> 3;
    const int lc = (tid & 7) * 4;

    float acc[2][8][4];
#pragma unroll
    for (int mt = 0; mt < 2; mt++)
#pragma unroll
        for (int nt = 0; nt < 8; nt++)
#pragma unroll
            for (int i = 0; i < 4; i++) acc[mt][nt][i] = 0.f;

    const int NT = K >> 5;

    float4 pa0, pa1, pa2, pa3, pw0, pw1, pw2, pw3;
    pa0 = *(const float4*)(A + (size_t)(m0 + lr0) * K + lc);
    pa1 = *(const float4*)(A + (size_t)(m0 + lr1) * K + lc);
    pa2 = *(const float4*)(A + (size_t)(m0 + lr2) * K + lc);
    pa3 = *(const float4*)(A + (size_t)(m0 + lr3) * K + lc);
    pw0 = *(const float4*)(W + (size_t)(n0 + lr0) * K + lc);
    pw1 = *(const float4*)(W + (size_t)(n0 + lr1) * K + lc);
    pw2 = *(const float4*)(W + (size_t)(n0 + lr2) * K + lc);
    pw3 = *(const float4*)(W + (size_t)(n0 + lr3) * K + lc);

#define STORE_TILE(buf)                                                                    \
    do {                                                                                   \
        uint32_t* Ab_ = As + (buf) * 4608;                                                 \
        uint32_t* Wb_ = Ws + (buf) * 4608;                                                 \
        *(uint4*)&Ab_[lr0 * 36 + lc] = make_uint4(f2tf32(pa0.x), f2tf32(pa0.y), f2tf32(pa0.z), f2tf32(pa0.w)); \
        *(uint4*)&Ab_[lr1 * 36 + lc] = make_uint4(f2tf32(pa1.x), f2tf32(pa1.y), f2tf32(pa1.z), f2tf32(pa1.w)); \
        *(uint4*)&Ab_[lr2 * 36 + lc] = make_uint4(f2tf32(pa2.x), f2tf32(pa2.y), f2tf32(pa2.z), f2tf32(pa2.w)); \
        *(uint4*)&Ab_[lr3 * 36 + lc] = make_uint4(f2tf32(pa3.x), f2tf32(pa3.y), f2tf32(pa3.z), f2tf32(pa3.w)); \
        *(uint4*)&Wb_[lr0 * 36 + lc] = make_uint4(f2tf32(pw0.x), f2tf32(pw0.y), f2tf32(pw0.z), f2tf32(pw0.w)); \
        *(uint4*)&Wb_[lr1 * 36 + lc] = make_uint4(f2tf32(pw1.x), f2tf32(pw1.y), f2tf32(pw1.z), f2tf32(pw1.w)); \
        *(uint4*)&Wb_[lr2 * 36 + lc] = make_uint4(f2tf32(pw2.x), f2tf32(pw2.y), f2tf32(pw2.z), f2tf32(pw2.w)); \
        *(uint4*)&Wb_[lr3 * 36 + lc] = make_uint4(f2tf32(pw3.x), f2tf32(pw3.y), f2tf32(pw3.z), f2tf32(pw3.w)); \
    } while (0)

    STORE_TILE(0);

    for (int kt = 0; kt < NT; kt++) {
        __syncthreads();
        if (kt + 1 < NT) {
            const int ko = (kt + 1) * 32;
            pa0 = *(const float4*)(A + (size_t)(m0 + lr0) * K + ko + lc);
            pa1 = *(const float4*)(A + (size_t)(m0 + lr1) * K + ko + lc);
            pa2 = *(const float4*)(A + (size_t)(m0 + lr2) * K + ko + lc);
            pa3 = *(const float4*)(A + (size_t)(m0 + lr3) * K + ko + lc);
            pw0 = *(const float4*)(W + (size_t)(n0 + lr0) * K + ko + lc);
            pw1 = *(const float4*)(W + (size_t)(n0 + lr1) * K + ko + lc);
            pw2 = *(const float4*)(W + (size_t)(n0 + lr2) * K + ko + lc);
            pw3 = *(const float4*)(W + (size_t)(n0 + lr3) * K + ko + lc);
        }

        const uint32_t* Ab = As + (kt & 1) * 4608;
        const uint32_t* Wb = Ws + (kt & 1) * 4608;
#pragma unroll
        for (int kk = 0; kk < 4; kk++) {
            const int c0 = kk * 8 + (lane & 3);
            uint32_t a[2][4];
#pragma unroll
            for (int mt = 0; mt < 2; mt++) {
                int r0 = rm + mt * 16 + (lane >> 2);
                a[mt][0] = Ab[r0 * 36 + c0];
                a[mt][1] = Ab[(r0 + 8) * 36 + c0];
                a[mt][2] = Ab[r0 * 36 + c0 + 4];
                a[mt][3] = Ab[(r0 + 8) * 36 + c0 + 4];
            }
            uint32_t b[8][2];
#pragma unroll
            for (int nt = 0; nt < 8; nt++) {
                int rb = cn + nt * 8 + (lane >> 2);
                b[nt][0] = Wb[rb * 36 + c0];
                b[nt][1] = Wb[rb * 36 + c0 + 4];
            }
#pragma unroll
            for (int mt = 0; mt < 2; mt++)
#pragma unroll
                for (int nt = 0; nt < 8; nt++) mma8(acc[mt][nt], a[mt], b[nt]);
        }

        if (kt + 1 < NT) STORE_TILE((kt + 1) & 1);
    }

#pragma unroll
    for (int mt = 0; mt < 2; mt++) {
#pragma unroll
        for (int nt = 0; nt < 8; nt++) {
#pragma unroll
            for (int half = 0; half < 2; half++) {
                int row = m0 + rm + mt * 16 + (lane >> 2) + half * 8;
                int col = n0 + cn + nt * 8 + 2 * (lane & 3);
                float v0 = acc[mt][nt][half * 2 + 0];
                float v1 = acc[mt][nt][half * 2 + 1];
                if (resid) {
                    v0 += resid[(size_t)row * DM_ + col];
                    v1 += resid[(size_t)row * DM_ + col + 1];
                }
                if (headmajor) {
                    int b = row >> 11, s = row & (S_ - 1);
                    int h = col >> 6, d = col & (D_ - 1);
                    float2* p = (float2*)&C[((((size_t)(b * H_ + h)) * S_) + s) * D_ + d];
                    *p = make_float2(v0, v1);
                } else {
                    float2* p = (float2*)&C[(size_t)row * DM_ + col];
                    *p = make_float2(v0, v1);
                }
            }
        }
    }
#undef STORE_TILE
}

// =================================================================================
// Attention pass A v2: 128 threads, 4 warps, warp = 32 q-rows (2 row-pairs).
// K/Vt b-fragments loaded ONCE per kk-chunk, reused across both row-pairs:
// halves the dominant smem fragment traffic vs the 8-warp/16-row layout.
// =================================================================================
__global__ __launch_bounds__(128, 2) void attn_a_tf32_kernel(
    const float* __restrict__ QH, const float* __restrict__ KH,
    const float* __restrict__ VH, float* __restrict__ AO,
    float* __restrict__ Mv, float* __restrict__ Lv) {
    extern __shared__ uint32_t sm[];
    uint32_t* Qs = sm;                    // [128][68] tf32, pre-scaled
    uint32_t* Ks = Qs + 128 * 68;         // [64 key][68 d]
    uint32_t* Vt = Ks + 64 * 68;          // [64 d][68 key]

    const int tid = threadIdx.x;
    const int lane = tid & 31, warp = tid >> 5;
    const int g = lane >> 2, t = lane & 3;
    const int r0 = warp * 32 + g;         // base q row for mt=0 (mt=1 adds 16)
    const int bh = blockIdx.y;
    const int q0 = blockIdx.x * 128;
    const int srcA = (lane & ~3) | (t >> 1);
    const int srcB = srcA + 2;

    const float* Qp = QH + (size_t)bh * S_ * D_;
    const float* Kp = KH + (size_t)bh * S_ * D_;
    const float* Vp = VH + (size_t)bh * S_ * D_;

    // load Q tile (128x64), folding SCALE_ (exact x2^-3): 2048 f4 slots / 128 thr
#pragma unroll
    for (int p = 0; p < 16; p++) {
        int idx = tid + p * 128;
        int r = idx >> 4, c4 = (idx & 15) * 4;
        float4 v = *(const float4*)(Qp + (size_t)(q0 + r) * D_ + c4);
        *(uint4*)&Qs[r * 68 + c4] = make_uint4(f2tf32(v.x * SCALE_), f2tf32(v.y * SCALE_),
                                               f2tf32(v.z * SCALE_), f2tf32(v.w * SCALE_));
    }

    float o[2][8][4];
#pragma unroll
    for (int mt = 0; mt < 2; mt++)
#pragma unroll
        for (int nt = 0; nt < 8; nt++)
#pragma unroll
            for (int i = 0; i < 4; i++) o[mt][nt][i] = 0.f;

    float rowm[2][2] = {{-1e30f, -1e30f}, {-1e30f, -1e30f}};
    float rowl[2][2] = {{0.f, 0.f}, {0.f, 0.f}};

    for (int kt = 0; kt < S_ / 64; kt++) {
        const int k0 = kt * 64;
        __syncthreads();
        // K tile: 1024 f4 slots / 128 thr
#pragma unroll
        for (int p = 0; p < 8; p++) {
            int idx = tid + p * 128;
            int r = idx >> 4, c4 = (idx & 15) * 4;
            float4 kv = *(const float4*)(Kp + (size_t)(k0 + r) * D_ + c4);
            *(uint4*)&Ks[r * 68 + c4] = make_uint4(f2tf32(kv.x), f2tf32(kv.y), f2tf32(kv.z), f2tf32(kv.w));
        }
        // Vt transpose, lane-major key (conflict-free)
#pragma unroll
        for (int p = 0; p < 8; p++) {
            int idx = tid + p * 128;
            int r = idx & 63, d4 = (idx >> 6) * 4;
            float4 vv = *(const float4*)(Vp + (size_t)(k0 + r) * D_ + d4);
            Vt[(d4 + 0) * 68 + r] = f2tf32(vv.x);
            Vt[(d4 + 1) * 68 + r] = f2tf32(vv.y);
            Vt[(d4 + 2) * 68 + r] = f2tf32(vv.z);
            Vt[(d4 + 3) * 68 + r] = f2tf32(vv.w);
        }
        __syncthreads();

        // ---- S = (Q*scale) @ K^T for both row-pairs; K b-frags loaded once -------
        float sacc[2][8][4];
#pragma unroll
        for (int mt = 0; mt < 2; mt++)
#pragma unroll
            for (int nt = 0; nt < 8; nt++)
#pragma unroll
                for (int i = 0; i < 4; i++) sacc[mt][nt][i] = 0.f;

#pragma unroll
        for (int kk = 0; kk < 8; kk++) {
            const int c0 = kk * 8 + t;
            uint32_t b[8][2];
#pragma unroll
            for (int nt = 0; nt < 8; nt++) {
                int rb = nt * 8 + g;
                b[nt][0] = Ks[rb * 68 + c0];
                b[nt][1] = Ks[rb * 68 + c0 + 4];
            }
#pragma unroll
            for (int mt = 0; mt < 2; mt++) {
                const int rm_ = r0 + mt * 16;
                uint32_t a[4];
                a[0] = Qs[rm_ * 68 + c0];
                a[1] = Qs[(rm_ + 8) * 68 + c0];
                a[2] = Qs[rm_ * 68 + c0 + 4];
                a[3] = Qs[(rm_ + 8) * 68 + c0 + 4];
#pragma unroll
                for (int nt = 0; nt < 8; nt++) mma8(sacc[mt][nt], a, b[nt]);
            }
        }

        // ---- register online softmax (4 rows per lane: mt x half) ----------------
#pragma unroll
        for (int mt = 0; mt < 2; mt++) {
            float mx0 = -1e30f, mx1 = -1e30f;
#pragma unroll
            for (int nt = 0; nt < 8; nt++) {
                mx0 = fmaxf(mx0, fmaxf(sacc[mt][nt][0], sacc[mt][nt][1]));
                mx1 = fmaxf(mx1, fmaxf(sacc[mt][nt][2], sacc[mt][nt][3]));
            }
            mx0 = fmaxf(mx0, __shfl_xor_sync(0xffffffffu, mx0, 1));
            mx0 = fmaxf(mx0, __shfl_xor_sync(0xffffffffu, mx0, 2));
            mx1 = fmaxf(mx1, __shfl_xor_sync(0xffffffffu, mx1, 1));
            mx1 = fmaxf(mx1, __shfl_xor_sync(0xffffffffu, mx1, 2));

            float mn0 = fmaxf(rowm[mt][0], mx0), mn1 = fmaxf(rowm[mt][1], mx1);
            float cr0 = __expf(rowm[mt][0] - mn0), cr1 = __expf(rowm[mt][1] - mn1);
            float ps0 = 0.f, ps1 = 0.f;
#pragma unroll
            for (int nt = 0; nt < 8; nt++) {
                sacc[mt][nt][0] = __expf(sacc[mt][nt][0] - mn0); ps0 += sacc[mt][nt][0];
                sacc[mt][nt][1] = __expf(sacc[mt][nt][1] - mn0); ps0 += sacc[mt][nt][1];
                sacc[mt][nt][2] = __expf(sacc[mt][nt][2] - mn1); ps1 += sacc[mt][nt][2];
                sacc[mt][nt][3] = __expf(sacc[mt][nt][3] - mn1); ps1 += sacc[mt][nt][3];
            }
            ps0 += __shfl_xor_sync(0xffffffffu, ps0, 1);
            ps0 += __shfl_xor_sync(0xffffffffu, ps0, 2);
            ps1 += __shfl_xor_sync(0xffffffffu, ps1, 1);
            ps1 += __shfl_xor_sync(0xffffffffu, ps1, 2);
            rowl[mt][0] = rowl[mt][0] * cr0 + ps0; rowm[mt][0] = mn0;
            rowl[mt][1] = rowl[mt][1] * cr1 + ps1; rowm[mt][1] = mn1;

#pragma unroll
            for (int nt = 0; nt < 8; nt++) {
                o[mt][nt][0] *= cr0; o[mt][nt][1] *= cr0;
                o[mt][nt][2] *= cr1; o[mt][nt][3] *= cr1;
            }
        }

        // ---- O += P @ V: Vt b-frags loaded once, reused across row-pairs ---------
#pragma unroll
        for (int kc = 0; kc < 8; kc++) {
            const int c0 = kc * 8 + t;
            uint32_t b[8][2];
#pragma unroll
            for (int nt = 0; nt < 8; nt++) {
                int rb = nt * 8 + g;
                b[nt][0] = Vt[rb * 68 + c0];
                b[nt][1] = Vt[rb * 68 + c0 + 4];
            }
#pragma unroll
            for (int mt = 0; mt < 2; mt++) {
                uint32_t p0 = f2tf32(sacc[mt][kc][0]);
                uint32_t p1 = f2tf32(sacc[mt][kc][1]);
                uint32_t p2 = f2tf32(sacc[mt][kc][2]);
                uint32_t p3 = f2tf32(sacc[mt][kc][3]);
                uint32_t pa[4];
                uint32_t u0 = __shfl_sync(0xffffffffu, p0, srcA);
                uint32_t u1 = __shfl_sync(0xffffffffu, p1, srcA);
                pa[0] = (lane & 1) ? u1 : u0;
                u0 = __shfl_sync(0xffffffffu, p2, srcA);
                u1 = __shfl_sync(0xffffffffu, p3, srcA);
                pa[1] = (lane & 1) ? u1 : u0;
                u0 = __shfl_sync(0xffffffffu, p0, srcB);
                u1 = __shfl_sync(0xffffffffu, p1, srcB);
                pa[2] = (lane & 1) ? u1 : u0;
                u0 = __shfl_sync(0xffffffffu, p2, srcB);
                u1 = __shfl_sync(0xffffffffu, p3, srcB);
                pa[3] = (lane & 1) ? u1 : u0;
#pragma unroll
                for (int nt = 0; nt < 8; nt++) mma8(o[mt][nt], pa, b[nt]);
            }
        }
    }

    // ---- epilogue -----------------------------------------------------------------
    const int bb = bh >> 4, hh = bh & 15;
#pragma unroll
    for (int mt = 0; mt < 2; mt++) {
        const int rm_ = r0 + mt * 16;
        float il0 = 1.f / rowl[mt][0], il1 = 1.f / rowl[mt][1];
#pragma unroll
        for (int nt = 0; nt < 8; nt++) {
            int col = hh * D_ + nt * 8 + 2 * t;
            size_t base0 = ((size_t)bb * S_ + (q0 + rm_)) * DM_ + col;
            size_t base1 = ((size_t)bb * S_ + (q0 + rm_ + 8)) * DM_ + col;
            *(float2*)&AO[base0] = make_float2(o[mt][nt][0] * il0, o[mt][nt][1] * il0);
            *(float2*)&AO[base1] = make_float2(o[mt][nt][2] * il1, o[mt][nt][3] * il1);
        }
        if (t == 0) {
            size_t mb = (size_t)bh * S_ + q0 + rm_;
            Mv[mb] = rowm[mt][0];     Lv[mb] = rowl[mt][0];
            Mv[mb + 8] = rowm[mt][1]; Lv[mb + 8] = rowl[mt][1];
        }
    }
}

// =================================================================================
// Attention pass B: recompute scores via mma, write attn = exp(s - m)/l.
// =================================================================================
__global__ __launch_bounds__(256) void attn_b_tf32_kernel(
    const float* __restrict__ QH, const float* __restrict__ KH,
    const float* __restrict__ Mv, const float* __restrict__ Lv,
    float* __restrict__ attn) {
    extern __shared__ uint32_t sm[];
    uint32_t* Qs = sm;               // [128][68]
    uint32_t* Ks = Qs + 128 * 68;    // [128][68]
    float* fm = (float*)(Ks + 128 * 68);
    float* fl = fm + 128;

    const int tid = threadIdx.x;
    const int lane = tid & 31, warp = tid >> 5;
    const int wm = warp >> 1, wn = warp & 1;
    const int rm = wm * 32, cn = wn * 64;
    const int bh = blockIdx.z;
    const int q0 = blockIdx.y * 128;
    const int k0 = blockIdx.x * 128;

    const float* Qp = QH + (size_t)bh * S_ * D_;
    const float* Kp = KH + (size_t)bh * S_ * D_;

#pragma unroll
    for (int p = 0; p < 8; p++) {
        int idx = tid + p * 256;
        int r = idx >> 4, c4 = (idx & 15) * 4;
        float4 qv = *(const float4*)(Qp + (size_t)(q0 + r) * D_ + c4);
        float4 kv = *(const float4*)(Kp + (size_t)(k0 + r) * D_ + c4);
        *(uint4*)&Qs[r * 68 + c4] = make_uint4(f2tf32(qv.x * SCALE_), f2tf32(qv.y * SCALE_),
                                               f2tf32(qv.z * SCALE_), f2tf32(qv.w * SCALE_));
        *(uint4*)&Ks[r * 68 + c4] = make_uint4(f2tf32(kv.x), f2tf32(kv.y), f2tf32(kv.z), f2tf32(kv.w));
    }
    if (tid < 128) {
        fm[tid] = Mv[(size_t)bh * S_ + q0 + tid];
        fl[tid] = 1.f / Lv[(size_t)bh * S_ + q0 + tid];
    }
    __syncthreads();

    float acc[2][8][4];
#pragma unroll
    for (int mt = 0; mt < 2; mt++)
#pragma unroll
        for (int nt = 0; nt < 8; nt++)
#pragma unroll
            for (int i = 0; i < 4; i++) acc[mt][nt][i] = 0.f;

#pragma unroll
    for (int kk = 0; kk < 8; kk++) {
        const int c0 = kk * 8 + (lane & 3);
        uint32_t a[2][4];
#pragma unroll
        for (int mt = 0; mt < 2; mt++) {
            int r0 = rm + mt * 16 + (lane >> 2);
            a[mt][0] = Qs[r0 * 68 + c0];
            a[mt][1] = Qs[(r0 + 8) * 68 + c0];
            a[mt][2] = Qs[r0 * 68 + c0 + 4];
            a[mt][3] = Qs[(r0 + 8) * 68 + c0 + 4];
        }
        uint32_t b[8][2];
#pragma unroll
        for (int nt = 0; nt < 8; nt++) {
            int rb = cn + nt * 8 + (lane >> 2);
            b[nt][0] = Ks[rb * 68 + c0];
            b[nt][1] = Ks[rb * 68 + c0 + 4];
        }
#pragma unroll
        for (int mt = 0; mt < 2; mt++)
#pragma unroll
            for (int nt = 0; nt < 8; nt++) mma8(acc[mt][nt], a[mt], b[nt]);
    }

#pragma unroll
    for (int mt = 0; mt < 2; mt++) {
#pragma unroll
        for (int half = 0; half < 2; half++) {
            int r0 = rm + mt * 16 + (lane >> 2) + half * 8;
            float m = fm[r0], il = fl[r0];
            size_t rowbase = ((size_t)bh * S_ + (q0 + r0)) * S_ + k0;
#pragma unroll
            for (int nt = 0; nt < 8; nt++) {
                int c = cn + nt * 8 + 2 * (lane & 3);
                float2 v;
                v.x = __expf(acc[mt][nt][half * 2 + 0] - m) * il;
                v.y = __expf(acc[mt][nt][half * 2 + 1] - m) * il;
                *(float2*)&attn[rowbase + c] = v;
            }
        }
    }
}

// =================================================================================
// LayerNorm over last dim (1024).
// =================================================================================
__global__ void ln_kernel(const float* __restrict__ FC, const float* __restrict__ gamma,
                          const float* __restrict__ beta, float* __restrict__ out) {
    __shared__ float sbuf[32];
    const int row = blockIdx.x;
    const int tid = threadIdx.x;
    const float* x = FC + (size_t)row * DM_;

    float v[4];
    float s = 0.f;
#pragma unroll
    for (int i = 0; i < 4; i++) { v[i] = x[tid + i * 256]; s += v[i]; }
    {
        int lane = tid & 31, wid = tid >> 5;
        for (int o = 16; o > 0; o >>= 1) s += __shfl_down_sync(0xffffffffu, s, o);
        if (lane == 0) sbuf[wid] = s;
        __syncthreads();
        if (wid == 0) {
            float tt = (lane < 8) ? sbuf[lane] : 0.f;
            for (int o = 4; o > 0; o >>= 1) tt += __shfl_down_sync(0xffffffffu, tt, o);
            if (lane == 0) sbuf[0] = tt;
        }
        __syncthreads();
    }
    float mu = sbuf[0] * (1.f / DM_);
    __syncthreads();

    float s2 = 0.f;
#pragma unroll
    for (int i = 0; i < 4; i++) { float d = v[i] - mu; s2 += d * d; }
    {
        int lane = tid & 31, wid = tid >> 5;
        for (int o = 16; o > 0; o >>= 1) s2 += __shfl_down_sync(0xffffffffu, s2, o);
        if (lane == 0) sbuf[wid] = s2;
        __syncthreads();
        if (wid == 0) {
            float tt = (lane < 8) ? sbuf[lane] : 0.f;
            for (int o = 4; o > 0; o >>= 1) tt += __shfl_down_sync(0xffffffffu, tt, o);
            if (lane == 0) sbuf[0] = tt;
        }
        __syncthreads();
    }
    float inv = rsqrtf(sbuf[0] * (1.f / DM_) + EPS_);

#pragma unroll
    for (int i = 0; i < 4; i++) {
        int c = tid + i * 256;
        out[(size_t)row * DM_ + c] = (v[i] - mu) * inv * gamma[c] + beta[c];
    }
}

// =================================================================================
// Launch — fork/join concurrency inside graph capture.
// =================================================================================
#define SMEM_A_BYTES ((128*68 + 64*68 + 64*68) * 4)
#define SMEM_B_BYTES ((128*68 + 128*68 + 2*128) * 4)

extern "C" void kernel_launch(void* const* d_in, const int* in_sizes, int n_in,
                              void* d_out, int out_size) {
    const float* q     = (const float*)d_in[0];
    const float* k     = (const float*)d_in[1];
    const float* v     = (const float*)d_in[2];
    const float* w_q   = (const float*)d_in[3];
    const float* w_k   = (const float*)d_in[4];
    const float* w_v   = (const float*)d_in[5];
    const float* w_fc  = (const float*)d_in[6];
    const float* gamma = (const float*)d_in[7];
    const float* beta  = (const float*)d_in[8];

    float* out  = (float*)d_out;
    float* attn = out + OUT_ELEMS;

    void *pQH, *pKH, *pVH, *pAO, *pFC, *pM, *pL;
    cudaGetSymbolAddress(&pQH, g_QH);
    cudaGetSymbolAddress(&pKH, g_KH);
    cudaGetSymbolAddress(&pVH, g_VH);
    cudaGetSymbolAddress(&pAO, g_AO);
    cudaGetSymbolAddress(&pFC, g_FC);
    cudaGetSymbolAddress(&pM, g_M);
    cudaGetSymbolAddress(&pL, g_L);
    float* QH = (float*)pQH; float* KH = (float*)pKH; float* VH = (float*)pVH;
    float* AO = (float*)pAO; float* FC = (float*)pFC;
    float* Mv = (float*)pM;  float* Lv = (float*)pL;

    static cudaStream_t s2 = nullptr, s3 = nullptr;
    static cudaEvent_t ev0 = nullptr, ev2, ev3, evA, evB;
    static bool attrs_set = false;
    if (!s2) {
        cudaStreamCreateWithFlags(&s2, cudaStreamNonBlocking);
        cudaStreamCreateWithFlags(&s3, cudaStreamNonBlocking);
        cudaEventCreateWithFlags(&ev0, cudaEventDisableTiming);
        cudaEventCreateWithFlags(&ev2, cudaEventDisableTiming);
        cudaEventCreateWithFlags(&ev3, cudaEventDisableTiming);
        cudaEventCreateWithFlags(&evA, cudaEventDisableTiming);
        cudaEventCreateWithFlags(&evB, cudaEventDisableTiming);
    }
    if (!attrs_set) {
        cudaFuncSetAttribute(gemm_tf32_kernel, cudaFuncAttributeMaxDynamicSharedMemorySize, GEMM_SMEM_BYTES);
        cudaFuncSetAttribute(attn_a_tf32_kernel, cudaFuncAttributeMaxDynamicSharedMemorySize, SMEM_A_BYTES);
        cudaFuncSetAttribute(attn_b_tf32_kernel, cudaFuncAttributeMaxDynamicSharedMemorySize, SMEM_B_BYTES);
        attrs_set = true;
    }

    dim3 gemm_grid(DM_ / 128, M8_ / 128);   // (8, 64)
    const bool want_attn = (size_t)out_size >= OUT_ELEMS + ATTN_ELEMS;

    // fork: projections in parallel
    cudaEventRecord(ev0, 0);
    cudaStreamWaitEvent(s2, ev0, 0);
    cudaStreamWaitEvent(s3, ev0, 0);
    gemm_tf32_kernel<<<gemm_grid, 256, GEMM_SMEM_BYTES, 0>>>(q, w_q, QH, DM_, 1, nullptr);
    gemm_tf32_kernel<<<gemm_grid, 256, GEMM_SMEM_BYTES, s2>>>(k, w_k, KH, DM_, 1, nullptr);
    gemm_tf32_kernel<<<gemm_grid, 256, GEMM_SMEM_BYTES, s3>>>(v, w_v, VH, DM_, 1, nullptr);
    cudaEventRecord(ev2, s2);
    cudaEventRecord(ev3, s3);
    cudaStreamWaitEvent(0, ev2, 0);
    cudaStreamWaitEvent(0, ev3, 0);

    // pass A: flash attention -> AO + (m, l)   (128 threads, 4 warps, 32 rows/warp)
    attn_a_tf32_kernel<<<dim3(S_ / 128, BH_), 128, SMEM_A_BYTES, 0>>>(QH, KH, VH, AO, Mv, Lv);

    // fork: attn_b (write-heavy) concurrent with fc+ln (compute-heavy)
    cudaEventRecord(evA, 0);
    if (want_attn) {
        cudaStreamWaitEvent(s2, evA, 0);
        attn_b_tf32_kernel<<<dim3(S_ / 128, S_ / 128, BH_), 256, SMEM_B_BYTES, s2>>>(QH, KH, Mv, Lv, attn);
        cudaEventRecord(evB, s2);
    }

    gemm_tf32_kernel<<<gemm_grid, 256, GEMM_SMEM_BYTES, 0>>>(AO, w_fc, FC, DM_, 0, q);
    ln_kernel<<<M8_, 256, 0, 0>>>(FC, gamma, beta, out);

    if (want_attn) {
        cudaStreamWaitEvent(0, evB, 0);   // join before returning to harness
    }
}

// round 9
// speedup vs baseline: 1.1564x; 1.1564x over previous
#include <cuda_runtime.h>
#include <cuda_bf16.h>
#include <math.h>
#include <stdint.h>

// Problem constants
#define B_ 4
#define S_ 2048
#define H_ 16
#define D_ 64
#define DM_ 1024
#define M8_ 8192
#define BH_ 64
#define SCALE_ 0.125f
#define EPS_ 1e-6f

#define OUT_ELEMS   (M8_ * DM_)
#define ATTN_ELEMS  ((size_t)BH_ * S_ * S_)

// ---------------- device scratch -----------------------------------------------
// QH/KH/VH hold tf32-ROUNDED fp32 bit patterns (QH additionally pre-scaled by 1/8).
__device__ float g_QH[(size_t)BH_ * S_ * D_];   // [B,H,S,D]
__device__ float g_KH[(size_t)BH_ * S_ * D_];
__device__ float g_VH[(size_t)BH_ * S_ * D_];
__device__ float g_AO[(size_t)M8_ * DM_];       // [B,S,H*D] fp32
__device__ float g_FC[(size_t)M8_ * DM_];
__device__ float g_M[(size_t)BH_ * S_];
__device__ float g_L[(size_t)BH_ * S_];

// ---------------- tf32 helpers ---------------------------------------------------
// cvt.rna REQUIRED for values not already tf32 (biased truncation -> R5 failure).
// Values already rounded to tf32 may be fed raw (truncation is then exact).
__device__ __forceinline__ uint32_t f2tf32(float x) {
    uint32_t u;
    asm("cvt.rna.tf32.f32 %0, %1;" : "=r"(u) : "f"(x));
    return u;
}

__device__ __forceinline__ void mma8(float* c, const uint32_t* a, const uint32_t* b) {
    asm volatile(
        "mma.sync.aligned.m16n8k8.row.col.f32.tf32.tf32.f32 "
        "{%0,%1,%2,%3}, {%4,%5,%6,%7}, {%8,%9}, {%0,%1,%2,%3};"
        : "+f"(c[0]), "+f"(c[1]), "+f"(c[2]), "+f"(c[3])
        : "r"(a[0]), "r"(a[1]), "r"(a[2]), "r"(a[3]), "r"(b[0]), "r"(b[1]));
}

__device__ __forceinline__ void cp16(uint32_t saddr, const void* g) {
    asm volatile("cp.async.cg.shared.global [%0], [%1], 16;" :: "r"(saddr), "l"(g));
}
__device__ __forceinline__ void cp_commit() {
    asm volatile("cp.async.commit_group;");
}

// =================================================================================
// tf32 GEMM: C[M,N] = A[M,K] @ W[N,K]^T (+resid). 128x128 tile, BK=32, 256 thr.
// headmajor path additionally rounds the output to tf32 (scaled by oscale) so
// attention kernels can consume it with zero conversions.
// =================================================================================
#define GEMM_SMEM_BYTES (4 * 128 * 36 * 4)

__global__ __launch_bounds__(256) void gemm_tf32_kernel(
    const float* __restrict__ A, const float* __restrict__ W, float* __restrict__ C,
    int K, int headmajor, const float* __restrict__ resid, float oscale) {
    extern __shared__ uint32_t dynsm[];
    uint32_t* As = dynsm;
    uint32_t* Ws = dynsm + 2 * 4608;

    const int tid = threadIdx.x;
    const int lane = tid & 31, warp = tid >> 5;
    const int wm = warp >> 1, wn = warp & 1;
    const int rm = wm * 32, cn = wn * 64;
    const int m0 = blockIdx.y * 128, n0 = blockIdx.x * 128;

    const int lr0 = tid >> 3, lr1 = (tid + 256) >> 3, lr2 = (tid + 512) >> 3, lr3 = (tid + 768) >> 3;
    const int lc = (tid & 7) * 4;

    float acc[2][8][4];
#pragma unroll
    for (int mt = 0; mt < 2; mt++)
#pragma unroll
        for (int nt = 0; nt < 8; nt++)
#pragma unroll
            for (int i = 0; i < 4; i++) acc[mt][nt][i] = 0.f;

    const int NT = K >> 5;

    float4 pa0, pa1, pa2, pa3, pw0, pw1, pw2, pw3;
    pa0 = *(const float4*)(A + (size_t)(m0 + lr0) * K + lc);
    pa1 = *(const float4*)(A + (size_t)(m0 + lr1) * K + lc);
    pa2 = *(const float4*)(A + (size_t)(m0 + lr2) * K + lc);
    pa3 = *(const float4*)(A + (size_t)(m0 + lr3) * K + lc);
    pw0 = *(const float4*)(W + (size_t)(n0 + lr0) * K + lc);
    pw1 = *(const float4*)(W + (size_t)(n0 + lr1) * K + lc);
    pw2 = *(const float4*)(W + (size_t)(n0 + lr2) * K + lc);
    pw3 = *(const float4*)(W + (size_t)(n0 + lr3) * K + lc);

#define STORE_TILE(buf)                                                                    \
    do {                                                                                   \
        uint32_t* Ab_ = As + (buf) * 4608;                                                 \
        uint32_t* Wb_ = Ws + (buf) * 4608;                                                 \
        *(uint4*)&Ab_[lr0 * 36 + lc] = make_uint4(f2tf32(pa0.x), f2tf32(pa0.y), f2tf32(pa0.z), f2tf32(pa0.w)); \
        *(uint4*)&Ab_[lr1 * 36 + lc] = make_uint4(f2tf32(pa1.x), f2tf32(pa1.y), f2tf32(pa1.z), f2tf32(pa1.w)); \
        *(uint4*)&Ab_[lr2 * 36 + lc] = make_uint4(f2tf32(pa2.x), f2tf32(pa2.y), f2tf32(pa2.z), f2tf32(pa2.w)); \
        *(uint4*)&Ab_[lr3 * 36 + lc] = make_uint4(f2tf32(pa3.x), f2tf32(pa3.y), f2tf32(pa3.z), f2tf32(pa3.w)); \
        *(uint4*)&Wb_[lr0 * 36 + lc] = make_uint4(f2tf32(pw0.x), f2tf32(pw0.y), f2tf32(pw0.z), f2tf32(pw0.w)); \
        *(uint4*)&Wb_[lr1 * 36 + lc] = make_uint4(f2tf32(pw1.x), f2tf32(pw1.y), f2tf32(pw1.z), f2tf32(pw1.w)); \
        *(uint4*)&Wb_[lr2 * 36 + lc] = make_uint4(f2tf32(pw2.x), f2tf32(pw2.y), f2tf32(pw2.z), f2tf32(pw2.w)); \
        *(uint4*)&Wb_[lr3 * 36 + lc] = make_uint4(f2tf32(pw3.x), f2tf32(pw3.y), f2tf32(pw3.z), f2tf32(pw3.w)); \
    } while (0)

    STORE_TILE(0);

    for (int kt = 0; kt < NT; kt++) {
        __syncthreads();
        if (kt + 1 < NT) {
            const int ko = (kt + 1) * 32;
            pa0 = *(const float4*)(A + (size_t)(m0 + lr0) * K + ko + lc);
            pa1 = *(const float4*)(A + (size_t)(m0 + lr1) * K + ko + lc);
            pa2 = *(const float4*)(A + (size_t)(m0 + lr2) * K + ko + lc);
            pa3 = *(const float4*)(A + (size_t)(m0 + lr3) * K + ko + lc);
            pw0 = *(const float4*)(W + (size_t)(n0 + lr0) * K + ko + lc);
            pw1 = *(const float4*)(W + (size_t)(n0 + lr1) * K + ko + lc);
            pw2 = *(const float4*)(W + (size_t)(n0 + lr2) * K + ko + lc);
            pw3 = *(const float4*)(W + (size_t)(n0 + lr3) * K + ko + lc);
        }

        const uint32_t* Ab = As + (kt & 1) * 4608;
        const uint32_t* Wb = Ws + (kt & 1) * 4608;
#pragma unroll
        for (int kk = 0; kk < 4; kk++) {
            const int c0 = kk * 8 + (lane & 3);
            uint32_t a[2][4];
#pragma unroll
            for (int mt = 0; mt < 2; mt++) {
                int r0 = rm + mt * 16 + (lane >> 2);
                a[mt][0] = Ab[r0 * 36 + c0];
                a[mt][1] = Ab[(r0 + 8) * 36 + c0];
                a[mt][2] = Ab[r0 * 36 + c0 + 4];
                a[mt][3] = Ab[(r0 + 8) * 36 + c0 + 4];
            }
            uint32_t b[8][2];
#pragma unroll
            for (int nt = 0; nt < 8; nt++) {
                int rb = cn + nt * 8 + (lane >> 2);
                b[nt][0] = Wb[rb * 36 + c0];
                b[nt][1] = Wb[rb * 36 + c0 + 4];
            }
#pragma unroll
            for (int mt = 0; mt < 2; mt++)
#pragma unroll
                for (int nt = 0; nt < 8; nt++) mma8(acc[mt][nt], a[mt], b[nt]);
        }

        if (kt + 1 < NT) STORE_TILE((kt + 1) & 1);
    }

#pragma unroll
    for (int mt = 0; mt < 2; mt++) {
#pragma unroll
        for (int nt = 0; nt < 8; nt++) {
#pragma unroll
            for (int half = 0; half < 2; half++) {
                int row = m0 + rm + mt * 16 + (lane >> 2) + half * 8;
                int col = n0 + cn + nt * 8 + 2 * (lane & 3);
                float v0 = acc[mt][nt][half * 2 + 0];
                float v1 = acc[mt][nt][half * 2 + 1];
                if (resid) {
                    v0 += resid[(size_t)row * DM_ + col];
                    v1 += resid[(size_t)row * DM_ + col + 1];
                }
                if (headmajor) {
                    // round (and scale) so downstream mma can consume raw bits
                    v0 = __uint_as_float(f2tf32(v0 * oscale));
                    v1 = __uint_as_float(f2tf32(v1 * oscale));
                    int b = row >> 11, s = row & (S_ - 1);
                    int h = col >> 6, d = col & (D_ - 1);
                    float2* p = (float2*)&C[((((size_t)(b * H_ + h)) * S_) + s) * D_ + d];
                    *p = make_float2(v0, v1);
                } else {
                    float2* p = (float2*)&C[(size_t)row * DM_ + col];
                    *p = make_float2(v0, v1);
                }
            }
        }
    }
#undef STORE_TILE
}

// =================================================================================
// Attention pass A v3: R7 layout (256 thr, 8 warps, 16 q-rows/warp) + cp.async
// 2-stage K/V pipeline. Inputs pre-rounded tf32 (Q pre-scaled) -> zero cvts on
// operand loads. V kept [key][d] (stride 72): PV b-frags read conflict-free,
// no transpose scatter.
// smem words: Qs[128*68]=8704 | Ks0,Ks1[64*68]=4352 ea | Vs0,Vs1[64*72]=4608 ea
// =================================================================================
#define AA_SMEM_BYTES ((8704 + 2*4352 + 2*4608) * 4)   // 106496 B

__global__ __launch_bounds__(256, 2) void attn_a_tf32_kernel(
    const float* __restrict__ QH, const float* __restrict__ KH,
    const float* __restrict__ VH, float* __restrict__ AO,
    float* __restrict__ Mv, float* __restrict__ Lv) {
    extern __shared__ uint32_t sm[];
    const uint32_t sbase = (uint32_t)__cvta_generic_to_shared(sm);

    const int tid = threadIdx.x;
    const int lane = tid & 31, warp = tid >> 5;
    const int g = lane >> 2, t = lane & 3;
    const int r0 = warp * 16 + g;
    const int bh = blockIdx.y;
    const int q0 = blockIdx.x * 128;
    const int srcA = (lane & ~3) | (t >> 1);
    const int srcB = srcA + 2;

    const float* Qp = QH + (size_t)bh * S_ * D_;
    const float* Kp = KH + (size_t)bh * S_ * D_;
    const float* Vp = VH + (size_t)bh * S_ * D_;

    const int NT = S_ / 64;

    // per-thread f4 slot for K/V fills
    // K tile: 1024 f4 slots; V tile: 1024 f4 slots
#define ISSUE_KV(stage, k0_)                                                          \
    do {                                                                              \
        _Pragma("unroll")                                                             \
        for (int p = 0; p < 4; p++) {                                                 \
            int idx = tid + p * 256;                                                  \
            int r = idx >> 4, c4 = (idx & 15) * 4;                                    \
            cp16(sbase + (uint32_t)((8704 + (stage) * 4352) + r * 68 + c4) * 4,       \
                 Kp + (size_t)((k0_) + r) * D_ + c4);                                 \
            cp16(sbase + (uint32_t)((17408 + (stage) * 4608) + r * 72 + c4) * 4,      \
                 Vp + (size_t)((k0_) + r) * D_ + c4);                                 \
        }                                                                             \
        cp_commit();                                                                  \
    } while (0)

    // G0: Q + KV stage0
#pragma unroll
    for (int p = 0; p < 8; p++) {
        int idx = tid + p * 256;
        int r = idx >> 4, c4 = (idx & 15) * 4;
        cp16(sbase + (uint32_t)(r * 68 + c4) * 4, Qp + (size_t)(q0 + r) * D_ + c4);
    }
#pragma unroll
    for (int p = 0; p < 4; p++) {
        int idx = tid + p * 256;
        int r = idx >> 4, c4 = (idx & 15) * 4;
        cp16(sbase + (uint32_t)(8704 + r * 68 + c4) * 4, Kp + (size_t)r * D_ + c4);
        cp16(sbase + (uint32_t)(17408 + r * 72 + c4) * 4, Vp + (size_t)r * D_ + c4);
    }
    cp_commit();
    // G1: KV stage1
    ISSUE_KV(1, 64);

    const uint32_t* Qs = sm;

    float o[8][4];
#pragma unroll
    for (int nt = 0; nt < 8; nt++)
#pragma unroll
        for (int i = 0; i < 4; i++) o[nt][i] = 0.f;

    float rowm0 = -1e30f, rowm1 = -1e30f;
    float rowl0 = 0.f, rowl1 = 0.f;

    for (int kt = 0; kt < NT; kt++) {
        if (kt + 1 < NT) asm volatile("cp.async.wait_group 1;");
        else             asm volatile("cp.async.wait_group 0;");
        __syncthreads();

        const uint32_t* Kb = sm + 8704 + (kt & 1) * 4352;
        const uint32_t* Vb = sm + 17408 + (kt & 1) * 4608;

        // ---- S = Qs @ K^T (Q pre-scaled) ----------------------------------------
        float sacc[8][4];
#pragma unroll
        for (int nt = 0; nt < 8; nt++)
#pragma unroll
            for (int i = 0; i < 4; i++) sacc[nt][i] = 0.f;

#pragma unroll
        for (int kk = 0; kk < 8; kk++) {
            const int c0 = kk * 8 + t;
            uint32_t a[4];
            a[0] = Qs[r0 * 68 + c0];
            a[1] = Qs[(r0 + 8) * 68 + c0];
            a[2] = Qs[r0 * 68 + c0 + 4];
            a[3] = Qs[(r0 + 8) * 68 + c0 + 4];
#pragma unroll
            for (int nt = 0; nt < 8; nt++) {
                int rb = nt * 8 + g;
                uint32_t b[2] = {Kb[rb * 68 + c0], Kb[rb * 68 + c0 + 4]};
                mma8(sacc[nt], a, b);
            }
        }

        // ---- register online softmax --------------------------------------------
        float mx0 = -1e30f, mx1 = -1e30f;
#pragma unroll
        for (int nt = 0; nt < 8; nt++) {
            mx0 = fmaxf(mx0, fmaxf(sacc[nt][0], sacc[nt][1]));
            mx1 = fmaxf(mx1, fmaxf(sacc[nt][2], sacc[nt][3]));
        }
        mx0 = fmaxf(mx0, __shfl_xor_sync(0xffffffffu, mx0, 1));
        mx0 = fmaxf(mx0, __shfl_xor_sync(0xffffffffu, mx0, 2));
        mx1 = fmaxf(mx1, __shfl_xor_sync(0xffffffffu, mx1, 1));
        mx1 = fmaxf(mx1, __shfl_xor_sync(0xffffffffu, mx1, 2));

        float mn0 = fmaxf(rowm0, mx0), mn1 = fmaxf(rowm1, mx1);
        float cr0 = __expf(rowm0 - mn0), cr1 = __expf(rowm1 - mn1);
        float ps0 = 0.f, ps1 = 0.f;
#pragma unroll
        for (int nt = 0; nt < 8; nt++) {
            sacc[nt][0] = __expf(sacc[nt][0] - mn0); ps0 += sacc[nt][0];
            sacc[nt][1] = __expf(sacc[nt][1] - mn0); ps0 += sacc[nt][1];
            sacc[nt][2] = __expf(sacc[nt][2] - mn1); ps1 += sacc[nt][2];
            sacc[nt][3] = __expf(sacc[nt][3] - mn1); ps1 += sacc[nt][3];
        }
        ps0 += __shfl_xor_sync(0xffffffffu, ps0, 1);
        ps0 += __shfl_xor_sync(0xffffffffu, ps0, 2);
        ps1 += __shfl_xor_sync(0xffffffffu, ps1, 1);
        ps1 += __shfl_xor_sync(0xffffffffu, ps1, 2);
        rowl0 = rowl0 * cr0 + ps0; rowm0 = mn0;
        rowl1 = rowl1 * cr1 + ps1; rowm1 = mn1;

#pragma unroll
        for (int nt = 0; nt < 8; nt++) {
            o[nt][0] *= cr0; o[nt][1] *= cr0;
            o[nt][2] *= cr1; o[nt][3] *= cr1;
        }

        // ---- O += P @ V: V read as [key][d] stride 72, conflict-free -------------
#pragma unroll
        for (int kc = 0; kc < 8; kc++) {
            uint32_t p0 = f2tf32(sacc[kc][0]);
            uint32_t p1 = f2tf32(sacc[kc][1]);
            uint32_t p2 = f2tf32(sacc[kc][2]);
            uint32_t p3 = f2tf32(sacc[kc][3]);
            uint32_t pa[4];
            {
                uint32_t u0 = __shfl_sync(0xffffffffu, p0, srcA);
                uint32_t u1 = __shfl_sync(0xffffffffu, p1, srcA);
                pa[0] = (lane & 1) ? u1 : u0;
                u0 = __shfl_sync(0xffffffffu, p2, srcA);
                u1 = __shfl_sync(0xffffffffu, p3, srcA);
                pa[1] = (lane & 1) ? u1 : u0;
                u0 = __shfl_sync(0xffffffffu, p0, srcB);
                u1 = __shfl_sync(0xffffffffu, p1, srcB);
                pa[2] = (lane & 1) ? u1 : u0;
                u0 = __shfl_sync(0xffffffffu, p2, srcB);
                u1 = __shfl_sync(0xffffffffu, p3, srcB);
                pa[3] = (lane & 1) ? u1 : u0;
            }
            const int key0 = kc * 8 + t;
#pragma unroll
            for (int nt = 0; nt < 8; nt++) {
                int d_ = nt * 8 + g;
                uint32_t b[2] = {Vb[key0 * 72 + d_], Vb[(key0 + 4) * 72 + d_]};
                mma8(o[nt], pa, b);
            }
        }

        __syncthreads();   // all warps done with stage kt&1 before refill
        if (kt + 2 < NT) ISSUE_KV(kt & 1, (kt + 2) * 64);
    }
#undef ISSUE_KV

    // ---- epilogue -----------------------------------------------------------------
    const int bb = bh >> 4, hh = bh & 15;
    float il0 = 1.f / rowl0, il1 = 1.f / rowl1;
#pragma unroll
    for (int nt = 0; nt < 8; nt++) {
        int col = hh * D_ + nt * 8 + 2 * t;
        size_t base0 = ((size_t)bb * S_ + (q0 + r0)) * DM_ + col;
        size_t base1 = ((size_t)bb * S_ + (q0 + r0 + 8)) * DM_ + col;
        *(float2*)&AO[base0] = make_float2(o[nt][0] * il0, o[nt][1] * il0);
        *(float2*)&AO[base1] = make_float2(o[nt][2] * il1, o[nt][3] * il1);
    }
    if (t == 0) {
        size_t mb = (size_t)bh * S_ + q0 + r0;
        Mv[mb] = rowm0;     Lv[mb] = rowl0;
        Mv[mb + 8] = rowm1; Lv[mb + 8] = rowl1;
    }
}

// =================================================================================
// Attention pass B: cp.async Q/K (pre-rounded, Q pre-scaled), mma, exp, store.
// smem words: Qs[128*68]=8704 | Ks[128*68]=8704 | fm[128] fl[128]
// =================================================================================
#define AB_SMEM_BYTES ((8704 + 8704 + 256) * 4)

__global__ __launch_bounds__(256) void attn_b_tf32_kernel(
    const float* __restrict__ QH, const float* __restrict__ KH,
    const float* __restrict__ Mv, const float* __restrict__ Lv,
    float* __restrict__ attn) {
    extern __shared__ uint32_t sm[];
    const uint32_t sbase = (uint32_t)__cvta_generic_to_shared(sm);
    uint32_t* Qs = sm;
    uint32_t* Ks = sm + 8704;
    float* fm = (float*)(sm + 17408);
    float* fl = fm + 128;

    const int tid = threadIdx.x;
    const int lane = tid & 31, warp = tid >> 5;
    const int wm = warp >> 1, wn = warp & 1;
    const int rm = wm * 32, cn = wn * 64;
    const int bh = blockIdx.z;
    const int q0 = blockIdx.y * 128;
    const int k0 = blockIdx.x * 128;

    const float* Qp = QH + (size_t)bh * S_ * D_;
    const float* Kp = KH + (size_t)bh * S_ * D_;

#pragma unroll
    for (int p = 0; p < 8; p++) {
        int idx = tid + p * 256;
        int r = idx >> 4, c4 = (idx & 15) * 4;
        cp16(sbase + (uint32_t)(r * 68 + c4) * 4, Qp + (size_t)(q0 + r) * D_ + c4);
        cp16(sbase + (uint32_t)(8704 + r * 68 + c4) * 4, Kp + (size_t)(k0 + r) * D_ + c4);
    }
    cp_commit();
    if (tid < 128) {
        fm[tid] = Mv[(size_t)bh * S_ + q0 + tid];
        fl[tid] = 1.f / Lv[(size_t)bh * S_ + q0 + tid];
    }
    asm volatile("cp.async.wait_group 0;");
    __syncthreads();

    float acc[2][8][4];
#pragma unroll
    for (int mt = 0; mt < 2; mt++)
#pragma unroll
        for (int nt = 0; nt < 8; nt++)
#pragma unroll
            for (int i = 0; i < 4; i++) acc[mt][nt][i] = 0.f;

#pragma unroll
    for (int kk = 0; kk < 8; kk++) {
        const int c0 = kk * 8 + (lane & 3);
        uint32_t a[2][4];
#pragma unroll
        for (int mt = 0; mt < 2; mt++) {
            int r0 = rm + mt * 16 + (lane >> 2);
            a[mt][0] = Qs[r0 * 68 + c0];
            a[mt][1] = Qs[(r0 + 8) * 68 + c0];
            a[mt][2] = Qs[r0 * 68 + c0 + 4];
            a[mt][3] = Qs[(r0 + 8) * 68 + c0 + 4];
        }
        uint32_t b[8][2];
#pragma unroll
        for (int nt = 0; nt < 8; nt++) {
            int rb = cn + nt * 8 + (lane >> 2);
            b[nt][0] = Ks[rb * 68 + c0];
            b[nt][1] = Ks[rb * 68 + c0 + 4];
        }
#pragma unroll
        for (int mt = 0; mt < 2; mt++)
#pragma unroll
            for (int nt = 0; nt < 8; nt++) mma8(acc[mt][nt], a[mt], b[nt]);
    }

#pragma unroll
    for (int mt = 0; mt < 2; mt++) {
#pragma unroll
        for (int half = 0; half < 2; half++) {
            int r0 = rm + mt * 16 + (lane >> 2) + half * 8;
            float m = fm[r0], il = fl[r0];
            size_t rowbase = ((size_t)bh * S_ + (q0 + r0)) * S_ + k0;
#pragma unroll
            for (int nt = 0; nt < 8; nt++) {
                int c = cn + nt * 8 + 2 * (lane & 3);
                float2 v;
                v.x = __expf(acc[mt][nt][half * 2 + 0] - m) * il;
                v.y = __expf(acc[mt][nt][half * 2 + 1] - m) * il;
                *(float2*)&attn[rowbase + c] = v;
            }
        }
    }
}

// =================================================================================
// LayerNorm over last dim (1024).
// =================================================================================
__global__ void ln_kernel(const float* __restrict__ FC, const float* __restrict__ gamma,
                          const float* __restrict__ beta, float* __restrict__ out) {
    __shared__ float sbuf[32];
    const int row = blockIdx.x;
    const int tid = threadIdx.x;
    const float* x = FC + (size_t)row * DM_;

    float v[4];
    float s = 0.f;
#pragma unroll
    for (int i = 0; i < 4; i++) { v[i] = x[tid + i * 256]; s += v[i]; }
    {
        int lane = tid & 31, wid = tid >> 5;
        for (int o = 16; o > 0; o >>= 1) s += __shfl_down_sync(0xffffffffu, s, o);
        if (lane == 0) sbuf[wid] = s;
        __syncthreads();
        if (wid == 0) {
            float tt = (lane < 8) ? sbuf[lane] : 0.f;
            for (int o = 4; o > 0; o >>= 1) tt += __shfl_down_sync(0xffffffffu, tt, o);
            if (lane == 0) sbuf[0] = tt;
        }
        __syncthreads();
    }
    float mu = sbuf[0] * (1.f / DM_);
    __syncthreads();

    float s2 = 0.f;
#pragma unroll
    for (int i = 0; i < 4; i++) { float d = v[i] - mu; s2 += d * d; }
    {
        int lane = tid & 31, wid = tid >> 5;
        for (int o = 16; o > 0; o >>= 1) s2 += __shfl_down_sync(0xffffffffu, s2, o);
        if (lane == 0) sbuf[wid] = s2;
        __syncthreads();
        if (wid == 0) {
            float tt = (lane < 8) ? sbuf[lane] : 0.f;
            for (int o = 4; o > 0; o >>= 1) tt += __shfl_down_sync(0xffffffffu, tt, o);
            if (lane == 0) sbuf[0] = tt;
        }
        __syncthreads();
    }
    float inv = rsqrtf(sbuf[0] * (1.f / DM_) + EPS_);

#pragma unroll
    for (int i = 0; i < 4; i++) {
        int c = tid + i * 256;
        out[(size_t)row * DM_ + c] = (v[i] - mu) * inv * gamma[c] + beta[c];
    }
}

// =================================================================================
// Launch — fork/join concurrency inside graph capture.
// =================================================================================
extern "C" void kernel_launch(void* const* d_in, const int* in_sizes, int n_in,
                              void* d_out, int out_size) {
    const float* q     = (const float*)d_in[0];
    const float* k     = (const float*)d_in[1];
    const float* v     = (const float*)d_in[2];
    const float* w_q   = (const float*)d_in[3];
    const float* w_k   = (const float*)d_in[4];
    const float* w_v   = (const float*)d_in[5];
    const float* w_fc  = (const float*)d_in[6];
    const float* gamma = (const float*)d_in[7];
    const float* beta  = (const float*)d_in[8];

    float* out  = (float*)d_out;
    float* attn = out + OUT_ELEMS;

    void *pQH, *pKH, *pVH, *pAO, *pFC, *pM, *pL;
    cudaGetSymbolAddress(&pQH, g_QH);
    cudaGetSymbolAddress(&pKH, g_KH);
    cudaGetSymbolAddress(&pVH, g_VH);
    cudaGetSymbolAddress(&pAO, g_AO);
    cudaGetSymbolAddress(&pFC, g_FC);
    cudaGetSymbolAddress(&pM, g_M);
    cudaGetSymbolAddress(&pL, g_L);
    float* QH = (float*)pQH; float* KH = (float*)pKH; float* VH = (float*)pVH;
    float* AO = (float*)pAO; float* FC = (float*)pFC;
    float* Mv = (float*)pM;  float* Lv = (float*)pL;

    static cudaStream_t s2 = nullptr, s3 = nullptr;
    static cudaEvent_t ev0 = nullptr, ev2, ev3, evA, evB;
    static bool attrs_set = false;
    if (!s2) {
        cudaStreamCreateWithFlags(&s2, cudaStreamNonBlocking);
        cudaStreamCreateWithFlags(&s3, cudaStreamNonBlocking);
        cudaEventCreateWithFlags(&ev0, cudaEventDisableTiming);
        cudaEventCreateWithFlags(&ev2, cudaEventDisableTiming);
        cudaEventCreateWithFlags(&ev3, cudaEventDisableTiming);
        cudaEventCreateWithFlags(&evA, cudaEventDisableTiming);
        cudaEventCreateWithFlags(&evB, cudaEventDisableTiming);
    }
    if (!attrs_set) {
        cudaFuncSetAttribute(gemm_tf32_kernel, cudaFuncAttributeMaxDynamicSharedMemorySize, GEMM_SMEM_BYTES);
        cudaFuncSetAttribute(attn_a_tf32_kernel, cudaFuncAttributeMaxDynamicSharedMemorySize, AA_SMEM_BYTES);
        cudaFuncSetAttribute(attn_b_tf32_kernel, cudaFuncAttributeMaxDynamicSharedMemorySize, AB_SMEM_BYTES);
        attrs_set = true;
    }

    dim3 gemm_grid(DM_ / 128, M8_ / 128);   // (8, 64)
    const bool want_attn = (size_t)out_size >= OUT_ELEMS + ATTN_ELEMS;

    // fork: projections in parallel (Q pre-scaled by 1/8; all rounded to tf32)
    cudaEventRecord(ev0, 0);
    cudaStreamWaitEvent(s2, ev0, 0);
    cudaStreamWaitEvent(s3, ev0, 0);
    gemm_tf32_kernel<<<gemm_grid, 256, GEMM_SMEM_BYTES, 0>>>(q, w_q, QH, DM_, 1, nullptr, SCALE_);
    gemm_tf32_kernel<<<gemm_grid, 256, GEMM_SMEM_BYTES, s2>>>(k, w_k, KH, DM_, 1, nullptr, 1.0f);
    gemm_tf32_kernel<<<gemm_grid, 256, GEMM_SMEM_BYTES, s3>>>(v, w_v, VH, DM_, 1, nullptr, 1.0f);
    cudaEventRecord(ev2, s2);
    cudaEventRecord(ev3, s3);
    cudaStreamWaitEvent(0, ev2, 0);
    cudaStreamWaitEvent(0, ev3, 0);

    // pass A: flash attention -> AO + (m, l)
    attn_a_tf32_kernel<<<dim3(S_ / 128, BH_), 256, AA_SMEM_BYTES, 0>>>(QH, KH, VH, AO, Mv, Lv);

    // fork: attn_b (write-heavy) concurrent with fc+ln (compute-heavy)
    cudaEventRecord(evA, 0);
    if (want_attn) {
        cudaStreamWaitEvent(s2, evA, 0);
        attn_b_tf32_kernel<<<dim3(S_ / 128, S_ / 128, BH_), 256, AB_SMEM_BYTES, s2>>>(QH, KH, Mv, Lv, attn);
        cudaEventRecord(evB, s2);
    }

    gemm_tf32_kernel<<<gemm_grid, 256, GEMM_SMEM_BYTES, 0>>>(AO, w_fc, FC, DM_, 0, q, 1.0f);
    ln_kernel<<<M8_, 256, 0, 0>>>(FC, gamma, beta, out);

    if (want_attn) {
        cudaStreamWaitEvent(0, evB, 0);   // join before returning to harness
    }
}